// round 14
// baseline (speedup 1.0000x reference)
#include <cuda_runtime.h>
#include <cuda_bf16.h>
#include <cuda_fp16.h>
#include <mma.h>
#include <cstdint>
#include <cstddef>

using namespace nvcuda;

#define BATCH 64
#define TLEN  512
#define EMBD  512
#define HID   1024
#define G4    4096
#define NTAG  10
#define ROWS  (BATCH*TLEN)          // 32768
#define RBLK  128                   // persistent blocks in recurrent kernel

// ---------------- cp.async helpers ----------------
__device__ __forceinline__ void cp16(void* dst, const void* src) {
    unsigned d = (unsigned)__cvta_generic_to_shared(dst);
    asm volatile("cp.async.cg.shared.global [%0], [%1], 16;\n" :: "r"(d), "l"(src));
}
__device__ __forceinline__ void cp_commit() { asm volatile("cp.async.commit_group;\n"); }
template<int N> __device__ __forceinline__ void cp_wait() {
    asm volatile("cp.async.wait_group %0;\n" :: "n"(N));
}
__device__ __forceinline__ float tanh_fast(float x) {
    float y; asm("tanh.approx.f32 %0, %1;" : "=f"(y) : "f"(x)); return y;
}

// ---------------- recur smem layout (halves unless noted) ----------------
#define RW_PITCH 1048                          // W_hh slice pitch (halves)
#define R_AP 40                                // staging panel pitch (halves)
#define R_AS_HALVES (2*4*64*R_AP)              // 20480 halves = 40960 B (2-deep ring)
#define R_PP 36                                // partial pitch (floats)
#define R_PS_FLOATS (4*64*R_PP)                // 9216 floats = 36864 B
// W_ih pitch/size depend on KIN (512 or 1024): RWI_PITCH = KIN + 24
#define R_SMEM_BYTES(KIN) (32*RW_PITCH*2 + 32*((KIN)+24)*2 + R_AS_HALVES*2 + R_PS_FLOATS*4)

// ---------------- device scratch (static: no allocations allowed) ----------------
__device__ __half g_seq0[(size_t)ROWS*EMBD];    // embeddings (half), t-major rows (t*64+b)
__device__ __half g_hseq[(size_t)ROWS*HID];     // layer-0 hidden sequence (half)
__device__ __half g_h[2][BATCH*HID];            // double-buffered recurrent h (half)
__device__ float  g_lasth[BATCH*HID];           // layer-1 h at t = lens-1 (fp32)
__device__ __half g_Wih0h[(size_t)G4*EMBD];     // gate-permuted fp16 weights
__device__ __half g_Whh0h[(size_t)G4*HID];
__device__ __half g_Wih1h[(size_t)G4*HID];
__device__ __half g_Whh1h[(size_t)G4*HID];
__device__ float  g_b0p[G4];
__device__ float  g_b1p[G4];
__device__ int    g_tt[BATCH];                  // target timestep per batch (lens-1)
__device__ unsigned g_barcnt = 0;               // monotonic grid-barrier ticket counter

// ---------------- grid barrier: monotonic ticket scheme (R7/R11-proven) -----------
// g_barcnt is always a multiple of RBLK between kernels, so the tickets of
// barrier k within a launch occupy [base+128k, base+128k+127] and
// target = (ticket/128 + 1)*128 needs no per-launch bookkeeping.
__device__ __forceinline__ void grid_barrier() {
    __syncthreads();
    if (threadIdx.x == 0) {
        __threadfence();                               // release our block's writes
        unsigned t = atomicAdd(&g_barcnt, 1u);
        unsigned target = ((t >> 7) + 1u) << 7;
        while ((int)(*(volatile unsigned*)&g_barcnt - target) < 0) {}
        __threadfence();                               // acquire
    }
    __syncthreads();
}

// ---------------- preprocessing ----------------
// Permute gate rows: out row 4*j+g  <-  in row g*HID+j, convert to fp16.
__global__ void permute_kernel(const float* __restrict__ Wih0, const float* __restrict__ Whh0,
                               const float* __restrict__ b0,
                               const float* __restrict__ Wih1, const float* __restrict__ Whh1,
                               const float* __restrict__ b1) {
    int p = blockIdx.x;                 // 0..4095
    int j = p >> 2, q = p & 3;
    size_t src = (size_t)(q * HID + j);
    for (int d = threadIdx.x; d < EMBD; d += blockDim.x)
        g_Wih0h[(size_t)p*EMBD + d] = __float2half_rn(Wih0[src*EMBD + d]);
    for (int d = threadIdx.x; d < HID; d += blockDim.x) {
        g_Whh0h[(size_t)p*HID + d] = __float2half_rn(Whh0[src*HID + d]);
        g_Wih1h[(size_t)p*HID + d] = __float2half_rn(Wih1[src*HID + d]);
        g_Whh1h[(size_t)p*HID + d] = __float2half_rn(Whh1[src*HID + d]);
    }
    if (threadIdx.x == 0) { g_b0p[p] = b0[src]; g_b1p[p] = b1[src]; }
}

// Embedding gather into t-major half layout: row r = t*64 + b
__global__ void embed_kernel(const int* __restrict__ x, const float* __restrict__ emb) {
    int r = blockIdx.x;
    int b = r & 63, t = r >> 6;
    int tok = x[b * TLEN + t];
    const float4* src = (const float4*)&emb[(size_t)tok * EMBD];
    __half2* dst = (__half2*)&g_seq0[(size_t)r * EMBD];
    float4 v = src[threadIdx.x];                 // 128 threads = 128 float4 = 512 floats
    dst[2 * threadIdx.x]     = __floats2half2_rn(v.x, v.y);
    dst[2 * threadIdx.x + 1] = __floats2half2_rn(v.z, v.w);
}

// lens + target timestep
__global__ void lens_kernel(const int* __restrict__ x) {
    __shared__ int red[8];
    int b = blockIdx.x;
    int c = 0;
    for (int t = threadIdx.x; t < TLEN; t += 256) c += (x[b * TLEN + t] == 0);
    #pragma unroll
    for (int o = 16; o > 0; o >>= 1) c += __shfl_down_sync(0xffffffffu, c, o);
    if ((threadIdx.x & 31) == 0) red[threadIdx.x >> 5] = c;
    __syncthreads();
    if (threadIdx.x == 0) {
        int tot = 0;
        #pragma unroll
        for (int w = 0; w < 8; w++) tot += red[w];
        int tt = TLEN - tot - 1;          // lens-1
        if (tt < 0) tt += TLEN;           // wrap like Python negative index
        g_tt[b] = tt;
    }
}

// ---------------- persistent recurrent kernel, FUSED input projection ----------
// R11 skeleton: 128 blocks x 256 threads; block bk owns permuted gate rows
// [32*bk, 32*bk+32) = hidden units [8*bk, 8*bk+8). 8 warps = 4 K-splits x 2
// M-halves, warp tile 32x32, warp-private 2-deep cp.async staging ring,
// barrier-free inner loop.
// NEW: gates(t) = inp(t) @ Wih^T + h(t-1) @ Whh^T + b computed in one kernel.
// The input-projection partial for step t+1 is computed AFTER writing h(t+1)
// and BEFORE the grid-barrier arrival — it depends only on the static input
// sequence, so it fills the barrier-wait shadow. Accumulators stay live
// across the barrier; the dependent h-part accumulates on top next iteration.
template<int KIN>
__global__ void __launch_bounds__(256) recur_kernel(const __half* __restrict__ Whh,
                                                    const __half* __restrict__ Wih,
                                                    const __half* __restrict__ inp,
                                                    const float* __restrict__ bias,
                                                    int mode) {
    constexpr int RWI_PITCH = KIN + 24;
    constexpr int KQ = KIN / 4;                     // input cols per K-split
    constexpr int NSS_IN = KIN / 128;               // input supersteps (4 or 8)

    extern __shared__ __half smh[];
    __half* Ws = smh;                               // [32][1048]      W_hh slice
    __half* Wi = Ws + 32 * RW_PITCH;                // [32][KIN+24]    W_ih slice
    __half* As = Wi + 32 * RWI_PITCH;               // [2][4][64][40]  staging ring
    float*  Ps = (float*)(As + R_AS_HALVES);        // [4][64][36] fp32 partials

    const int tid = threadIdx.x;
    const int warp = tid >> 5;
    const int lane = tid & 31;
    const int bk = blockIdx.x;
    const int ks = warp >> 1;                       // K-split 0..3
    const int mh = (warp & 1) * 32;                 // M half (batch rows)

    // ---- stage W_hh slice rows [32*bk, 32*bk+32), K=1024 halves ----
    for (int i = tid; i < 32 * 128; i += 256) {     // 128 x 16B per gate row
        int r = i >> 7, c = i & 127;
        float4 v = *(const float4*)((const char*)&Whh[((size_t)(32 * bk + r)) * HID] + c * 16);
        *(float4*)((char*)&Ws[r * RW_PITCH] + c * 16) = v;
    }
    // ---- stage W_ih slice rows [32*bk, 32*bk+32), K=KIN halves ----
    for (int i = tid; i < 32 * (KIN / 8); i += 256) {
        int r = i / (KIN / 8), c = i % (KIN / 8);
        float4 v = *(const float4*)((const char*)&Wih[((size_t)(32 * bk + r)) * KIN] + c * 16);
        *(float4*)((char*)&Wi[r * RWI_PITCH] + c * 16) = v;
    }
    // per-thread persistent state (pointwise mapping is static across steps)
    const int pb0 = tid >> 3, pj0 = tid & 7;
    const float4 bv = *(const float4*)&bias[32 * bk + pj0 * 4];
    const int tt0 = g_tt[pb0];
    const int tt1 = g_tt[pb0 + 32];
    float c0 = 0.0f, c1 = 0.0f;                     // cell states
    {   // zero this block's slice of g_h[0]
        int b = tid >> 2, j2 = (tid & 3) * 2;
        g_h[0][b * HID + 8 * bk + j2]     = __float2half(0.0f);
        g_h[0][b * HID + 8 * bk + j2 + 1] = __float2half(0.0f);
    }
    grid_barrier();                                 // W staged + h0 zeroed everywhere

    // warp-private staging geometry: 32 rows x 32 halves per superstep
    const int srow = lane >> 2;                     // 0..7  (+8 per i)
    const int scol = (lane & 3) << 3;               // 0,8,16,24 (halves)

    wmma::fragment<wmma::accumulator, 16, 16, 16, float> acc[2][2];

    // input-projection partial for step tin: acc = inp(tin) @ Wih^T (this
    // warp's K-split). Independent of h; runs in the barrier-wait shadow.
    auto input_mma = [&](int tin) {
        #pragma unroll
        for (int i = 0; i < 2; i++)
            #pragma unroll
            for (int j = 0; j < 2; j++) wmma::fill_fragment(acc[i][j], 0.0f);
        auto stage_in = [&](int buf, int ssi) {
            #pragma unroll
            for (int i = 0; i < 4; i++) {
                int row = mh + i * 8 + srow;
                cp16(&As[((buf * 4 + ks) * 64 + row) * R_AP + scol],
                     &inp[((size_t)(tin * 64) + row) * KIN + ks * KQ + ssi * 32 + scol]);
            }
            cp_commit();
        };
        stage_in(0, 0);
        stage_in(1, 1);
        #pragma unroll
        for (int ssi = 0; ssi < NSS_IN; ssi++) {
            if (ssi < NSS_IN - 1) cp_wait<1>(); else cp_wait<0>();
            __syncwarp();
            int buf = ssi & 1;
            #pragma unroll
            for (int kk = 0; kk < 2; kk++) {
                wmma::fragment<wmma::matrix_a, 16, 16, 16, __half, wmma::row_major> af[2];
                wmma::fragment<wmma::matrix_b, 16, 16, 16, __half, wmma::col_major> bf[2];
                #pragma unroll
                for (int mm = 0; mm < 2; mm++)
                    wmma::load_matrix_sync(af[mm],
                        &As[((buf * 4 + ks) * 64 + mh + mm * 16) * R_AP + kk * 16], R_AP);
                #pragma unroll
                for (int nn = 0; nn < 2; nn++)
                    wmma::load_matrix_sync(bf[nn],
                        &Wi[(nn * 16) * RWI_PITCH + ks * KQ + ssi * 32 + kk * 16], RWI_PITCH);
                #pragma unroll
                for (int mm = 0; mm < 2; mm++)
                    #pragma unroll
                    for (int nn = 0; nn < 2; nn++)
                        wmma::mma_sync(acc[mm][nn], af[mm], bf[nn], acc[mm][nn]);
            }
            if (ssi < NSS_IN - 2) stage_in(buf, ssi + 2);
        }
    };

    input_mma(0);                                   // prologue: acc = x_proj(0)

    for (int t = 0; t < TLEN; t++) {
        const __half* hprev = g_h[t & 1];
        __half* hnext = g_h[(t + 1) & 1];

        // ---- dependent part: acc += h(t) @ Whh^T (this warp's K-split) ----
        auto stage = [&](int buf, int ss) {
            #pragma unroll
            for (int i = 0; i < 4; i++) {
                int row = mh + i * 8 + srow;
                cp16(&As[((buf * 4 + ks) * 64 + row) * R_AP + scol],
                     &hprev[(size_t)row * HID + ks * 256 + ss * 32 + scol]);
            }
            cp_commit();
        };
        stage(0, 0);
        stage(1, 1);
        #pragma unroll
        for (int ss = 0; ss < 8; ss++) {
            if (ss < 7) cp_wait<1>(); else cp_wait<0>();
            __syncwarp();                           // staged data visible warp-wide
            int buf = ss & 1;
            #pragma unroll
            for (int kk = 0; kk < 2; kk++) {
                wmma::fragment<wmma::matrix_a, 16, 16, 16, __half, wmma::row_major> af[2];
                wmma::fragment<wmma::matrix_b, 16, 16, 16, __half, wmma::col_major> bf[2];
                #pragma unroll
                for (int mm = 0; mm < 2; mm++)
                    wmma::load_matrix_sync(af[mm],
                        &As[((buf * 4 + ks) * 64 + mh + mm * 16) * R_AP + kk * 16], R_AP);
                #pragma unroll
                for (int nn = 0; nn < 2; nn++)
                    wmma::load_matrix_sync(bf[nn],
                        &Ws[(nn * 16) * RW_PITCH + ks * 256 + ss * 32 + kk * 16], RW_PITCH);
                #pragma unroll
                for (int mm = 0; mm < 2; mm++)
                    #pragma unroll
                    for (int nn = 0; nn < 2; nn++)
                        wmma::mma_sync(acc[mm][nn], af[mm], bf[nn], acc[mm][nn]);
            }
            if (ss < 6) stage(buf, ss + 2);         // own subtile: no cross-warp hazard
        }

        // K-split partials -> Ps (separate fp32 region, no aliasing)
        #pragma unroll
        for (int mm = 0; mm < 2; mm++)
            #pragma unroll
            for (int nn = 0; nn < 2; nn++)
                wmma::store_matrix_sync(&Ps[(ks * 64 + mh + mm * 16) * R_PP + nn * 16],
                                        acc[mm][nn], R_PP, wmma::mem_row_major);
        __syncthreads();                            // cross-warp: partials ready

        // fused pointwise: sum 4 partials + bias, LSTM cell update
        #pragma unroll
        for (int it = 0; it < 2; it++) {
            int b = pb0 + it * 32;
            int jj = pj0;
            int col = jj * 4;
            float4 p0 = *(const float4*)&Ps[(0 * 64 + b) * R_PP + col];
            float4 p1 = *(const float4*)&Ps[(1 * 64 + b) * R_PP + col];
            float4 p2 = *(const float4*)&Ps[(2 * 64 + b) * R_PP + col];
            float4 p3 = *(const float4*)&Ps[(3 * 64 + b) * R_PP + col];
            float gi = p0.x + p1.x + p2.x + p3.x + bv.x;
            float gf = p0.y + p1.y + p2.y + p3.y + bv.y;
            float gg = p0.z + p1.z + p2.z + p3.z + bv.z;
            float go = p0.w + p1.w + p2.w + p3.w + bv.w;
            float c = it ? c1 : c0;
            float si = 1.0f / (1.0f + __expf(-gi));
            float sf = 1.0f / (1.0f + __expf(-gf));
            float so = 1.0f / (1.0f + __expf(-go));
            c = sf * c + si * tanh_fast(gg);
            if (it) c1 = c; else c0 = c;
            float h = so * tanh_fast(c);
            hnext[(size_t)b * HID + 8 * bk + jj] = __float2half(h);
            if (mode == 0)
                g_hseq[((size_t)(t * 64 + b)) * HID + 8 * bk + jj] = __float2half(h);
            else if (t == (it ? tt1 : tt0))
                g_lasth[(size_t)b * HID + 8 * bk + jj] = h;
        }

        // barrier-shadow work: input projection for step t+1 (independent)
        if (t + 1 < TLEN) input_mma(t + 1);

        grid_barrier();                             // h(t+1) visible; Ps safe to reuse
    }
}

// ---------------- output projection ----------------
__global__ void out_kernel(const float* __restrict__ Wout, const float* __restrict__ bout,
                           float* __restrict__ out) {
    __shared__ float red[4];
    int b = blockIdx.x, tag = blockIdx.y;
    float s = 0.0f;
    for (int k = threadIdx.x; k < HID; k += 128)
        s += g_lasth[b * HID + k] * Wout[tag * HID + k];
    #pragma unroll
    for (int o = 16; o > 0; o >>= 1) s += __shfl_down_sync(0xffffffffu, s, o);
    if ((threadIdx.x & 31) == 0) red[threadIdx.x >> 5] = s;
    __syncthreads();
    if (threadIdx.x == 0)
        out[b * NTAG + tag] = red[0] + red[1] + red[2] + red[3] + bout[tag];
}

// ---------------- launch ----------------
extern "C" void kernel_launch(void* const* d_in, const int* in_sizes, int n_in,
                              void* d_out, int out_size) {
    const int*   x    = (const int*)d_in[0];
    const float* emb  = (const float*)d_in[1];
    const float* Wih0 = (const float*)d_in[2];
    const float* Whh0 = (const float*)d_in[3];
    const float* b0   = (const float*)d_in[4];
    const float* Wih1 = (const float*)d_in[5];
    const float* Whh1 = (const float*)d_in[6];
    const float* b1   = (const float*)d_in[7];
    const float* Wout = (const float*)d_in[8];
    const float* bout = (const float*)d_in[9];
    float* out = (float*)d_out;

    cudaFuncSetAttribute(recur_kernel<EMBD>, cudaFuncAttributeMaxDynamicSharedMemorySize,
                         R_SMEM_BYTES(EMBD));
    cudaFuncSetAttribute(recur_kernel<HID>, cudaFuncAttributeMaxDynamicSharedMemorySize,
                         R_SMEM_BYTES(HID));

    __half *p_seq0, *p_hseq, *pWih0, *pWih1, *pWhh0, *pWhh1;
    float *pb0, *pb1;
    cudaGetSymbolAddress((void**)&p_seq0, g_seq0);
    cudaGetSymbolAddress((void**)&p_hseq, g_hseq);
    cudaGetSymbolAddress((void**)&pWih0,  g_Wih0h);
    cudaGetSymbolAddress((void**)&pWih1,  g_Wih1h);
    cudaGetSymbolAddress((void**)&pWhh0,  g_Whh0h);
    cudaGetSymbolAddress((void**)&pWhh1,  g_Whh1h);
    cudaGetSymbolAddress((void**)&pb0,    g_b0p);
    cudaGetSymbolAddress((void**)&pb1,    g_b1p);

    permute_kernel<<<G4, 256>>>(Wih0, Whh0, b0, Wih1, Whh1, b1);
    embed_kernel<<<ROWS, 128>>>(x, emb);
    lens_kernel<<<BATCH, 256>>>(x);

    // Layer 0 (input = embeddings, KIN = 512) — x_proj fused
    recur_kernel<EMBD><<<RBLK, 256, R_SMEM_BYTES(EMBD)>>>(pWhh0, pWih0, p_seq0, pb0, 0);

    // Layer 1 (input = layer-0 hidden sequence, KIN = 1024) — x_proj fused
    recur_kernel<HID><<<RBLK, 256, R_SMEM_BYTES(HID)>>>(pWhh1, pWih1, p_hseq, pb1, 1);

    // Output head
    out_kernel<<<dim3(BATCH, NTAG), 128>>>(Wout, bout, out);
}

// round 17
// speedup vs baseline: 1.1328x; 1.1328x over previous
#include <cuda_runtime.h>
#include <cuda_bf16.h>
#include <cuda_fp16.h>
#include <mma.h>
#include <cstdint>
#include <cstddef>

using namespace nvcuda;

#define BATCH 64
#define TLEN  512
#define EMBD  512
#define HID   1024
#define G4    4096
#define NTAG  10
#define ROWS  (BATCH*TLEN)          // 32768
#define RBLK  128                   // persistent blocks in recurrent kernel

// ---------------- cp.async helpers ----------------
__device__ __forceinline__ void cp16(void* dst, const void* src) {
    unsigned d = (unsigned)__cvta_generic_to_shared(dst);
    asm volatile("cp.async.cg.shared.global [%0], [%1], 16;\n" :: "r"(d), "l"(src));
}
__device__ __forceinline__ void cp_commit() { asm volatile("cp.async.commit_group;\n"); }
template<int N> __device__ __forceinline__ void cp_wait() {
    asm volatile("cp.async.wait_group %0;\n" :: "n"(N));
}
__device__ __forceinline__ float tanh_fast(float x) {
    float y; asm("tanh.approx.f32 %0, %1;" : "=f"(y) : "f"(x)); return y;
}

// ---------------- recur smem layout (halves unless noted) ----------------
#define RW_PITCH 1048                          // W_hh slice pitch (halves)
#define R_AP 40                                // staging panel pitch (halves)
#define R_AS_HALVES (2*4*64*R_AP)              // 20480 halves = 40960 B (2-deep ring)
#define R_PP 36                                // partial pitch (floats)
#define R_PS_FLOATS (4*64*R_PP)                // 9216 floats = 36864 B
// W_ih pitch/size depend on KIN (512 or 1024): RWI_PITCH = KIN + 24
#define R_SMEM_BYTES(KIN) (32*RW_PITCH*2 + 32*((KIN)+24)*2 + R_AS_HALVES*2 + R_PS_FLOATS*4)

// ---------------- device scratch (static: no allocations allowed) ----------------
__device__ __half g_seq0[(size_t)ROWS*EMBD];    // embeddings (half), t-major rows (t*64+b)
__device__ __half g_hseq[(size_t)ROWS*HID];     // layer-0 hidden sequence (half)
__device__ __half g_h[2][BATCH*HID];            // double-buffered recurrent h (half)
__device__ float  g_lasth[BATCH*HID];           // layer-1 h at t = lens-1 (fp32)
__device__ __half g_Wih0h[(size_t)G4*EMBD];     // gate-permuted fp16 weights
__device__ __half g_Whh0h[(size_t)G4*HID];
__device__ __half g_Wih1h[(size_t)G4*HID];
__device__ __half g_Whh1h[(size_t)G4*HID];
__device__ float  g_b0p[G4];
__device__ float  g_b1p[G4];
__device__ int    g_tt[BATCH];                  // target timestep per batch (lens-1)
__device__ unsigned g_barcnt = 0;               // monotonic grid-barrier ticket counter

// ---------------- grid barrier: monotonic ticket scheme (R7/R11-proven) -----------
// g_barcnt is always a multiple of RBLK between kernels, so the tickets of
// barrier k within a launch occupy [base+128k, base+128k+127] and
// target = (ticket/128 + 1)*128 needs no per-launch bookkeeping.
__device__ __forceinline__ void grid_barrier() {
    __syncthreads();
    if (threadIdx.x == 0) {
        __threadfence();                               // release our block's writes
        unsigned t = atomicAdd(&g_barcnt, 1u);
        unsigned target = ((t >> 7) + 1u) << 7;
        while ((int)(*(volatile unsigned*)&g_barcnt - target) < 0) {}
        __threadfence();                               // acquire
    }
    __syncthreads();
}

// ---------------- preprocessing ----------------
// Permute gate rows: out row 4*j+g  <-  in row g*HID+j, convert to fp16.
__global__ void permute_kernel(const float* __restrict__ Wih0, const float* __restrict__ Whh0,
                               const float* __restrict__ b0,
                               const float* __restrict__ Wih1, const float* __restrict__ Whh1,
                               const float* __restrict__ b1) {
    int p = blockIdx.x;                 // 0..4095
    int j = p >> 2, q = p & 3;
    size_t src = (size_t)(q * HID + j);
    for (int d = threadIdx.x; d < EMBD; d += blockDim.x)
        g_Wih0h[(size_t)p*EMBD + d] = __float2half_rn(Wih0[src*EMBD + d]);
    for (int d = threadIdx.x; d < HID; d += blockDim.x) {
        g_Whh0h[(size_t)p*HID + d] = __float2half_rn(Whh0[src*HID + d]);
        g_Wih1h[(size_t)p*HID + d] = __float2half_rn(Wih1[src*HID + d]);
        g_Whh1h[(size_t)p*HID + d] = __float2half_rn(Whh1[src*HID + d]);
    }
    if (threadIdx.x == 0) { g_b0p[p] = b0[src]; g_b1p[p] = b1[src]; }
}

// Embedding gather into t-major half layout: row r = t*64 + b
__global__ void embed_kernel(const int* __restrict__ x, const float* __restrict__ emb) {
    int r = blockIdx.x;
    int b = r & 63, t = r >> 6;
    int tok = x[b * TLEN + t];
    const float4* src = (const float4*)&emb[(size_t)tok * EMBD];
    __half2* dst = (__half2*)&g_seq0[(size_t)r * EMBD];
    float4 v = src[threadIdx.x];                 // 128 threads = 128 float4 = 512 floats
    dst[2 * threadIdx.x]     = __floats2half2_rn(v.x, v.y);
    dst[2 * threadIdx.x + 1] = __floats2half2_rn(v.z, v.w);
}

// lens + target timestep
__global__ void lens_kernel(const int* __restrict__ x) {
    __shared__ int red[8];
    int b = blockIdx.x;
    int c = 0;
    for (int t = threadIdx.x; t < TLEN; t += 256) c += (x[b * TLEN + t] == 0);
    #pragma unroll
    for (int o = 16; o > 0; o >>= 1) c += __shfl_down_sync(0xffffffffu, c, o);
    if ((threadIdx.x & 31) == 0) red[threadIdx.x >> 5] = c;
    __syncthreads();
    if (threadIdx.x == 0) {
        int tot = 0;
        #pragma unroll
        for (int w = 0; w < 8; w++) tot += red[w];
        int tt = TLEN - tot - 1;          // lens-1
        if (tt < 0) tt += TLEN;           // wrap like Python negative index
        g_tt[b] = tt;
    }
}

// ---------------- persistent recurrent kernel, FUSED input projection ----------
// R11 skeleton: 128 blocks x 256 threads; block bk owns permuted gate rows
// [32*bk, 32*bk+32) = hidden units [8*bk, 8*bk+8). 8 warps = 4 K-splits x 2
// M-halves, warp tile 32x32, warp-private 2-deep cp.async staging ring,
// barrier-free inner loop.
// gates(t) = inp(t) @ Wih^T + h(t-1) @ Whh^T + b computed in one kernel.
// FIX vs R13: the grid barrier is split into ARRIVE and WAIT, and the
// input-projection partial for the next step (independent of h) runs BETWEEN
// them — inside the poll window — instead of before arrival, so it overlaps
// barrier latency + inter-block skew rather than extending the critical path.
template<int KIN>
__global__ void __launch_bounds__(256) recur_kernel(const __half* __restrict__ Whh,
                                                    const __half* __restrict__ Wih,
                                                    const __half* __restrict__ inp,
                                                    const float* __restrict__ bias,
                                                    int mode) {
    constexpr int RWI_PITCH = KIN + 24;
    constexpr int KQ = KIN / 4;                     // input cols per K-split
    constexpr int NSS_IN = KIN / 128;               // input supersteps (4 or 8)

    extern __shared__ __half smh[];
    __half* Ws = smh;                               // [32][1048]      W_hh slice
    __half* Wi = Ws + 32 * RW_PITCH;                // [32][KIN+24]    W_ih slice
    __half* As = Wi + 32 * RWI_PITCH;               // [2][4][64][40]  staging ring
    float*  Ps = (float*)(As + R_AS_HALVES);        // [4][64][36] fp32 partials

    const int tid = threadIdx.x;
    const int warp = tid >> 5;
    const int lane = tid & 31;
    const int bk = blockIdx.x;
    const int ks = warp >> 1;                       // K-split 0..3
    const int mh = (warp & 1) * 32;                 // M half (batch rows)

    // ---- stage W_hh slice rows [32*bk, 32*bk+32), K=1024 halves ----
    for (int i = tid; i < 32 * 128; i += 256) {     // 128 x 16B per gate row
        int r = i >> 7, c = i & 127;
        float4 v = *(const float4*)((const char*)&Whh[((size_t)(32 * bk + r)) * HID] + c * 16);
        *(float4*)((char*)&Ws[r * RW_PITCH] + c * 16) = v;
    }
    // ---- stage W_ih slice rows [32*bk, 32*bk+32), K=KIN halves ----
    for (int i = tid; i < 32 * (KIN / 8); i += 256) {
        int r = i / (KIN / 8), c = i % (KIN / 8);
        float4 v = *(const float4*)((const char*)&Wih[((size_t)(32 * bk + r)) * KIN] + c * 16);
        *(float4*)((char*)&Wi[r * RWI_PITCH] + c * 16) = v;
    }
    // per-thread persistent state (pointwise mapping is static across steps)
    const int pb0 = tid >> 3, pj0 = tid & 7;
    const float4 bv = *(const float4*)&bias[32 * bk + pj0 * 4];
    const int tt0 = g_tt[pb0];
    const int tt1 = g_tt[pb0 + 32];
    float c0 = 0.0f, c1 = 0.0f;                     // cell states
    {   // zero this block's slice of g_h[0]
        int b = tid >> 2, j2 = (tid & 3) * 2;
        g_h[0][b * HID + 8 * bk + j2]     = __float2half(0.0f);
        g_h[0][b * HID + 8 * bk + j2 + 1] = __float2half(0.0f);
    }
    grid_barrier();                                 // W staged + h0 zeroed everywhere

    // warp-private staging geometry: 32 rows x 32 halves per superstep
    const int srow = lane >> 2;                     // 0..7  (+8 per i)
    const int scol = (lane & 3) << 3;               // 0,8,16,24 (halves)

    wmma::fragment<wmma::accumulator, 16, 16, 16, float> acc[2][2];

    // input-projection partial for step tin: acc = inp(tin) @ Wih^T (this
    // warp's K-split). Independent of h; runs inside the barrier poll window.
    auto input_mma = [&](int tin) {
        #pragma unroll
        for (int i = 0; i < 2; i++)
            #pragma unroll
            for (int j = 0; j < 2; j++) wmma::fill_fragment(acc[i][j], 0.0f);
        auto stage_in = [&](int buf, int ssi) {
            #pragma unroll
            for (int i = 0; i < 4; i++) {
                int row = mh + i * 8 + srow;
                cp16(&As[((buf * 4 + ks) * 64 + row) * R_AP + scol],
                     &inp[((size_t)(tin * 64) + row) * KIN + ks * KQ + ssi * 32 + scol]);
            }
            cp_commit();
        };
        stage_in(0, 0);
        stage_in(1, 1);
        #pragma unroll
        for (int ssi = 0; ssi < NSS_IN; ssi++) {
            if (ssi < NSS_IN - 1) cp_wait<1>(); else cp_wait<0>();
            __syncwarp();
            int buf = ssi & 1;
            #pragma unroll
            for (int kk = 0; kk < 2; kk++) {
                wmma::fragment<wmma::matrix_a, 16, 16, 16, __half, wmma::row_major> af[2];
                wmma::fragment<wmma::matrix_b, 16, 16, 16, __half, wmma::col_major> bf[2];
                #pragma unroll
                for (int mm = 0; mm < 2; mm++)
                    wmma::load_matrix_sync(af[mm],
                        &As[((buf * 4 + ks) * 64 + mh + mm * 16) * R_AP + kk * 16], R_AP);
                #pragma unroll
                for (int nn = 0; nn < 2; nn++)
                    wmma::load_matrix_sync(bf[nn],
                        &Wi[(nn * 16) * RWI_PITCH + ks * KQ + ssi * 32 + kk * 16], RWI_PITCH);
                #pragma unroll
                for (int mm = 0; mm < 2; mm++)
                    #pragma unroll
                    for (int nn = 0; nn < 2; nn++)
                        wmma::mma_sync(acc[mm][nn], af[mm], bf[nn], acc[mm][nn]);
            }
            if (ssi < NSS_IN - 2) stage_in(buf, ssi + 2);
        }
    };

    input_mma(0);                                   // prologue: acc = x_proj(0)

    for (int t = 0; t < TLEN; t++) {
        const __half* hprev = g_h[t & 1];
        __half* hnext = g_h[(t + 1) & 1];

        // ---- dependent part: acc += h(t) @ Whh^T (this warp's K-split) ----
        auto stage = [&](int buf, int ss) {
            #pragma unroll
            for (int i = 0; i < 4; i++) {
                int row = mh + i * 8 + srow;
                cp16(&As[((buf * 4 + ks) * 64 + row) * R_AP + scol],
                     &hprev[(size_t)row * HID + ks * 256 + ss * 32 + scol]);
            }
            cp_commit();
        };
        stage(0, 0);
        stage(1, 1);
        #pragma unroll
        for (int ss = 0; ss < 8; ss++) {
            if (ss < 7) cp_wait<1>(); else cp_wait<0>();
            __syncwarp();                           // staged data visible warp-wide
            int buf = ss & 1;
            #pragma unroll
            for (int kk = 0; kk < 2; kk++) {
                wmma::fragment<wmma::matrix_a, 16, 16, 16, __half, wmma::row_major> af[2];
                wmma::fragment<wmma::matrix_b, 16, 16, 16, __half, wmma::col_major> bf[2];
                #pragma unroll
                for (int mm = 0; mm < 2; mm++)
                    wmma::load_matrix_sync(af[mm],
                        &As[((buf * 4 + ks) * 64 + mh + mm * 16) * R_AP + kk * 16], R_AP);
                #pragma unroll
                for (int nn = 0; nn < 2; nn++)
                    wmma::load_matrix_sync(bf[nn],
                        &Ws[(nn * 16) * RW_PITCH + ks * 256 + ss * 32 + kk * 16], RW_PITCH);
                #pragma unroll
                for (int mm = 0; mm < 2; mm++)
                    #pragma unroll
                    for (int nn = 0; nn < 2; nn++)
                        wmma::mma_sync(acc[mm][nn], af[mm], bf[nn], acc[mm][nn]);
            }
            if (ss < 6) stage(buf, ss + 2);         // own subtile: no cross-warp hazard
        }

        // K-split partials -> Ps (separate fp32 region, no aliasing)
        #pragma unroll
        for (int mm = 0; mm < 2; mm++)
            #pragma unroll
            for (int nn = 0; nn < 2; nn++)
                wmma::store_matrix_sync(&Ps[(ks * 64 + mh + mm * 16) * R_PP + nn * 16],
                                        acc[mm][nn], R_PP, wmma::mem_row_major);
        __syncthreads();                            // cross-warp: partials ready

        // fused pointwise: sum 4 partials + bias, LSTM cell update
        #pragma unroll
        for (int it = 0; it < 2; it++) {
            int b = pb0 + it * 32;
            int jj = pj0;
            int col = jj * 4;
            float4 p0 = *(const float4*)&Ps[(0 * 64 + b) * R_PP + col];
            float4 p1 = *(const float4*)&Ps[(1 * 64 + b) * R_PP + col];
            float4 p2 = *(const float4*)&Ps[(2 * 64 + b) * R_PP + col];
            float4 p3 = *(const float4*)&Ps[(3 * 64 + b) * R_PP + col];
            float gi = p0.x + p1.x + p2.x + p3.x + bv.x;
            float gf = p0.y + p1.y + p2.y + p3.y + bv.y;
            float gg = p0.z + p1.z + p2.z + p3.z + bv.z;
            float go = p0.w + p1.w + p2.w + p3.w + bv.w;
            float c = it ? c1 : c0;
            float si = 1.0f / (1.0f + __expf(-gi));
            float sf = 1.0f / (1.0f + __expf(-gf));
            float so = 1.0f / (1.0f + __expf(-go));
            c = sf * c + si * tanh_fast(gg);
            if (it) c1 = c; else c0 = c;
            float h = so * tanh_fast(c);
            hnext[(size_t)b * HID + 8 * bk + jj] = __float2half(h);
            if (mode == 0)
                g_hseq[((size_t)(t * 64 + b)) * HID + 8 * bk + jj] = __float2half(h);
            else if (t == (it ? tt1 : tt0))
                g_lasth[(size_t)b * HID + 8 * bk + jj] = h;
        }

        // ---- grid barrier, SPLIT: arrive -> shadow work -> wait ----
        __syncthreads();                            // h(t+1)/Ps reads complete block-wide
        unsigned bar_target = 0;
        if (tid == 0) {
            __threadfence();                        // release h(t+1) writes
            unsigned tk = atomicAdd(&g_barcnt, 1u);
            bar_target = ((tk >> 7) + 1u) << 7;
        }

        // barrier-shadow: input projection for step t+1 (independent of h)
        if (t + 1 < TLEN) input_mma(t + 1);

        if (tid == 0) {
            while ((int)(*(volatile unsigned*)&g_barcnt - bar_target) < 0) {}
            __threadfence();                        // acquire
        }
        __syncthreads();                            // all see h(t+1); Ps reusable
    }
}

// ---------------- output projection ----------------
__global__ void out_kernel(const float* __restrict__ Wout, const float* __restrict__ bout,
                           float* __restrict__ out) {
    __shared__ float red[4];
    int b = blockIdx.x, tag = blockIdx.y;
    float s = 0.0f;
    for (int k = threadIdx.x; k < HID; k += 128)
        s += g_lasth[b * HID + k] * Wout[tag * HID + k];
    #pragma unroll
    for (int o = 16; o > 0; o >>= 1) s += __shfl_down_sync(0xffffffffu, s, o);
    if ((threadIdx.x & 31) == 0) red[threadIdx.x >> 5] = s;
    __syncthreads();
    if (threadIdx.x == 0)
        out[b * NTAG + tag] = red[0] + red[1] + red[2] + red[3] + bout[tag];
}

// ---------------- launch ----------------
extern "C" void kernel_launch(void* const* d_in, const int* in_sizes, int n_in,
                              void* d_out, int out_size) {
    const int*   x    = (const int*)d_in[0];
    const float* emb  = (const float*)d_in[1];
    const float* Wih0 = (const float*)d_in[2];
    const float* Whh0 = (const float*)d_in[3];
    const float* b0   = (const float*)d_in[4];
    const float* Wih1 = (const float*)d_in[5];
    const float* Whh1 = (const float*)d_in[6];
    const float* b1   = (const float*)d_in[7];
    const float* Wout = (const float*)d_in[8];
    const float* bout = (const float*)d_in[9];
    float* out = (float*)d_out;

    cudaFuncSetAttribute(recur_kernel<EMBD>, cudaFuncAttributeMaxDynamicSharedMemorySize,
                         R_SMEM_BYTES(EMBD));
    cudaFuncSetAttribute(recur_kernel<HID>, cudaFuncAttributeMaxDynamicSharedMemorySize,
                         R_SMEM_BYTES(HID));

    __half *p_seq0, *p_hseq, *pWih0, *pWih1, *pWhh0, *pWhh1;
    float *pb0, *pb1;
    cudaGetSymbolAddress((void**)&p_seq0, g_seq0);
    cudaGetSymbolAddress((void**)&p_hseq, g_hseq);
    cudaGetSymbolAddress((void**)&pWih0,  g_Wih0h);
    cudaGetSymbolAddress((void**)&pWih1,  g_Wih1h);
    cudaGetSymbolAddress((void**)&pWhh0,  g_Whh0h);
    cudaGetSymbolAddress((void**)&pWhh1,  g_Whh1h);
    cudaGetSymbolAddress((void**)&pb0,    g_b0p);
    cudaGetSymbolAddress((void**)&pb1,    g_b1p);

    permute_kernel<<<G4, 256>>>(Wih0, Whh0, b0, Wih1, Whh1, b1);
    embed_kernel<<<ROWS, 128>>>(x, emb);
    lens_kernel<<<BATCH, 256>>>(x);

    // Layer 0 (input = embeddings, KIN = 512) — x_proj fused, barrier-shadowed
    recur_kernel<EMBD><<<RBLK, 256, R_SMEM_BYTES(EMBD)>>>(pWhh0, pWih0, p_seq0, pb0, 0);

    // Layer 1 (input = layer-0 hidden sequence, KIN = 1024) — x_proj fused
    recur_kernel<HID><<<RBLK, 256, R_SMEM_BYTES(HID)>>>(pWhh1, pWih1, p_hseq, pb1, 1);

    // Output head
    out_kernel<<<dim3(BATCH, NTAG), 128>>>(Wout, bout, out);
}